// round 10
// baseline (speedup 1.0000x reference)
#include <cuda_runtime.h>
#include <cfloat>
#include <math.h>
#include <stdint.h>

// Problem constants (fixed shapes from reference)
#define BB 4
#define NN 4096
#define KK 20
#define QPB 16                // kNN queries per block (1 per warp, 512 threads)
#define PP (BB * NN * KK)     // 327680 positions
#define NB1 (PP / 256)        // layer1 blocks = 1280
#define NBG (PP / 128)        // gemm blocks   = 2560

// ---------------------------------------------------------------------------
// Scratch in __device__ globals (no allocation allowed in kernel_launch)
// ---------------------------------------------------------------------------
__device__ float g_y1[64  * PP];
__device__ float g_y2[128 * PP];
__device__ float g_y3[128 * PP];
__device__ int   g_idx[BB * NN * KK];
__device__ float g_ps[128 * NBG];
__device__ float g_pq[128 * NBG];
__device__ float g_sc1[64],  g_sh1[64];
__device__ float g_sc2[128], g_sh2[128];
__device__ float g_sc3[128], g_sh3[128];

// Orderable uint key: ascending float order -> ascending unsigned order.
__device__ __forceinline__ unsigned okey(float f) {
    unsigned u = __float_as_uint(f);
    return u ^ (((unsigned)((int)u >> 31)) | 0x80000000u);
}

// tf32 round-to-nearest (result bit-pattern is a valid fp32 with 10-bit mantissa)
__device__ __forceinline__ unsigned tf32_rna(float f) {
    unsigned r;
    asm("cvt.rna.tf32.f32 %0, %1;" : "=r"(r) : "f"(f));
    return r;
}

// m16n8k8 tf32 mma: D += A(16x8 row) * B(8x8 col)
__device__ __forceinline__ void mma_tf32(float* c,
                                         unsigned a0, unsigned a1,
                                         unsigned a2, unsigned a3,
                                         unsigned b0, unsigned b1) {
    asm("mma.sync.aligned.m16n8k8.row.col.f32.tf32.tf32.f32 "
        "{%0,%1,%2,%3}, {%4,%5,%6,%7}, {%8,%9}, {%0,%1,%2,%3};"
        : "+f"(c[0]), "+f"(c[1]), "+f"(c[2]), "+f"(c[3])
        : "r"(a0), "r"(a1), "r"(a2), "r"(a3), "r"(b0), "r"(b1));
}

// ---------------------------------------------------------------------------
// K0: warp-cooperative exact kNN (k=20), REDUX-based inserts (R9-proven).
// ---------------------------------------------------------------------------
__global__ void __launch_bounds__(512) knn_warp_kernel(
    const float* __restrict__ x, int* __restrict__ idxo)
{
    extern __shared__ float4 pts[];   // 4096 * 16B = 64KB
    const int b = blockIdx.y;
    const float* xb = x + (size_t)b * NN * 3;
    const int tid = threadIdx.x, lane = tid & 31, w = tid >> 5;

    for (int t = tid; t < NN; t += 512) {
        float px = xb[t * 3 + 0], py = xb[t * 3 + 1], pz = xb[t * 3 + 2];
        pts[t] = make_float4(px, py, pz, px * px + py * py + pz * pz);
    }
    __syncthreads();

    const int i = blockIdx.x * QPB + w;
    float4 q = pts[i];
    const float qx = 2.f * q.x, qy = 2.f * q.y, qz = 2.f * q.z;

    unsigned my_k = (lane < KK) ? okey(-FLT_MAX) : okey(FLT_MAX);
    int      my_j = 0x7fff0000 | lane;
    unsigned wkey = okey(-FLT_MAX);

    for (int jc = 0; jc < NN; jc += 32) {
        float4 p = pts[jc + lane];
        float s = fmaf(qx, p.x, fmaf(qy, p.y, fmaf(qz, p.z, -p.w)));
        unsigned k = okey(s);
        unsigned mask = __ballot_sync(0xffffffffu, k > wkey);
        while (mask) {
            const int l = __ffs(mask) - 1;
            mask &= mask - 1;
            const unsigned kc = __shfl_sync(0xffffffffu, k, l);
            if (kc > wkey) {
                const unsigned umin = __reduce_min_sync(0xffffffffu, my_k);
                const bool tied = (my_k == umin);
                const int jmax = __reduce_max_sync(0xffffffffu, tied ? my_j : -1);
                if (tied && my_j == jmax) { my_k = kc; my_j = jc + l; }
                wkey = __reduce_min_sync(0xffffffffu, my_k);
            }
        }
    }

    if (lane < KK)
        idxo[((size_t)b * NN + i) * KK + lane] = my_j;
}

// ---------------------------------------------------------------------------
// K1: edge features -> conv1 (64x6) + BN1 partials (proven version).
// ---------------------------------------------------------------------------
__global__ void __launch_bounds__(256) layer1_kernel(
    const float* __restrict__ x,
    const int* __restrict__ idx,
    const float* __restrict__ W1,
    const float* __restrict__ b1,
    float* __restrict__ y1,
    float* __restrict__ ps,
    float* __restrict__ pq)
{
    __shared__ float Wsh[64 * 6];
    __shared__ float bsh[64];
    __shared__ float s_s[64 * 8];
    __shared__ float s_q[64 * 8];
    for (int t = threadIdx.x; t < 64 * 6; t += blockDim.x) Wsh[t] = W1[t];
    if (threadIdx.x < 64) bsh[threadIdx.x] = b1[threadIdx.x];
    __syncthreads();

    const int tid  = threadIdx.x;
    const int lane = tid & 31;
    const int warp = tid >> 5;
    const int p  = blockIdx.x * 256 + tid;
    const int bn = p / KK;
    const int b  = bn / NN;
    const int j  = idx[p];

    const float* xi = x + (size_t)bn * 3;
    const float* xj = x + ((size_t)b * NN + j) * 3;
    float xi0 = xi[0], xi1 = xi[1], xi2 = xi[2];
    float f0 = xj[0] - xi0, f1 = xj[1] - xi1, f2 = xj[2] - xi2;

#pragma unroll 4
    for (int o = 0; o < 64; ++o) {
        const float* w = Wsh + o * 6;
        float a = bsh[o];
        a = fmaf(w[0], f0, a);
        a = fmaf(w[1], f1, a);
        a = fmaf(w[2], f2, a);
        a = fmaf(w[3], xi0, a);
        a = fmaf(w[4], xi1, a);
        a = fmaf(w[5], xi2, a);
        y1[(size_t)o * PP + p] = a;

        float s = a, q = a * a;
#pragma unroll
        for (int m = 16; m > 0; m >>= 1) {
            s += __shfl_xor_sync(0xffffffffu, s, m);
            q += __shfl_xor_sync(0xffffffffu, q, m);
        }
        if (lane == 0) { s_s[o * 8 + warp] = s; s_q[o * 8 + warp] = q; }
    }
    __syncthreads();

    if (tid < 64) {
        float acc = 0.f;
#pragma unroll
        for (int w = 0; w < 8; w++) acc += s_s[tid * 8 + w];
        ps[tid * NB1 + blockIdx.x] = acc;
    } else if (tid < 128) {
        const int o = tid - 64;
        float acc = 0.f;
#pragma unroll
        for (int w = 0; w < 8; w++) acc += s_q[o * 8 + w];
        pq[o * NB1 + blockIdx.x] = acc;
    }
}

// ---------------------------------------------------------------------------
// Reduce per-block partials -> fused BN affine (scale, shift).
// ---------------------------------------------------------------------------
__global__ void reduce_kernel(const float* __restrict__ ps,
                              const float* __restrict__ pq,
                              int nb,
                              const float* __restrict__ gamma,
                              const float* __restrict__ beta,
                              float* __restrict__ scale,
                              float* __restrict__ shift)
{
    const int c = blockIdx.x;
    double s = 0.0, q = 0.0;
    for (int i = threadIdx.x; i < nb; i += 256) {
        s += (double)ps[c * nb + i];
        q += (double)pq[c * nb + i];
    }
    __shared__ double r1[256], r2[256];
    r1[threadIdx.x] = s; r2[threadIdx.x] = q;
    __syncthreads();
    for (int off = 128; off > 0; off >>= 1) {
        if (threadIdx.x < off) {
            r1[threadIdx.x] += r1[threadIdx.x + off];
            r2[threadIdx.x] += r2[threadIdx.x + off];
        }
        __syncthreads();
    }
    if (threadIdx.x == 0) {
        double mean = r1[0] / (double)PP;
        double var  = r2[0] / (double)PP - mean * mean;
        double inv  = (double)gamma[c] / sqrt(var + 1e-5);
        scale[c] = (float)inv;
        shift[c] = (float)((double)beta[c] - mean * inv);
    }
}

// ---------------------------------------------------------------------------
// GEMM via mma.sync m16n8k8 tf32 with 3xTF32 split (near-fp32 accuracy).
// yout[o][p] = bias[o] + sum_c W[o][c] * relu(scale[c]*yin[c][p]+shift[c])
// Block: 256 thr (8 warps), tile 128o x 128p. Warp w: o-rows [16w,16w+16),
// all 128 p (two 64-wide halves). W and activations staged in smem as
// (hi,lo) tf32 pairs, stride 130 uint2 (conflict-free LDS.64).
// Epilogue: stores + deterministic BN partial sums.
// ---------------------------------------------------------------------------
template <int CIN>
__global__ void __launch_bounds__(256) gemm_mma_kernel(
    const float* __restrict__ yin,
    const float* __restrict__ W,
    const float* __restrict__ bias,
    const float* __restrict__ scale,
    const float* __restrict__ shift,
    float* __restrict__ yout,
    float* __restrict__ ps,
    float* __restrict__ pq)
{
    extern __shared__ uint2 sh2[];
    uint2* W2  = sh2;                 // [CIN][130]  (hi,lo) of W[o][c], indexed [c][o]
    uint2* Ash = sh2 + CIN * 130;     // [64][130]   (hi,lo) of activations [c][p]
    const int tid  = threadIdx.x;
    const int lane = tid & 31;
    const int warp = tid >> 5;
    const int gid  = lane >> 2;       // 0..7
    const int tig  = lane & 3;        // 0..3
    const int o0   = warp * 16;
    const int pbase = blockIdx.x * 128;

    // Stage W split (one-time)
    for (int t = tid; t < 128 * CIN; t += 256) {
        int o = t / CIN, c = t - o * CIN;
        float v = W[t];
        unsigned h = tf32_rna(v);
        unsigned l = tf32_rna(v - __uint_as_float(h));
        W2[c * 130 + o] = make_uint2(h, l);
    }

    float acc[2][8][4];
#pragma unroll
    for (int hf = 0; hf < 2; hf++)
#pragma unroll
        for (int t = 0; t < 8; t++)
#pragma unroll
            for (int r = 0; r < 4; r++) acc[hf][t][r] = 0.f;

#pragma unroll
    for (int kc = 0; kc < CIN / 64; ++kc) {
        __syncthreads();   // W2 ready (kc=0) / protect Ash before restage
        for (int t = tid; t < 64 * 128; t += 256) {
            int c = t >> 7, p = t & 127;
            int cg = kc * 64 + c;
            float v = fmaxf(fmaf(yin[(size_t)cg * PP + pbase + p],
                                 scale[cg], shift[cg]), 0.f);
            unsigned h = tf32_rna(v);
            unsigned l = tf32_rna(v - __uint_as_float(h));
            Ash[c * 130 + p] = make_uint2(h, l);
        }
        __syncthreads();

#pragma unroll
        for (int ks = 0; ks < 8; ++ks) {
            const int c0 = ks * 8;          // within chunk (activations)
            const int cw = kc * 64 + c0;    // global c (weights)
            // A fragments (W): a0 row=o0+gid col=c+tig; a1 row+8; a2/a3 col+4
            uint2 A0 = W2[(cw + tig) * 130 + o0 + gid];
            uint2 A1 = W2[(cw + tig) * 130 + o0 + gid + 8];
            uint2 A2 = W2[(cw + tig + 4) * 130 + o0 + gid];
            uint2 A3 = W2[(cw + tig + 4) * 130 + o0 + gid + 8];
#pragma unroll
            for (int hf = 0; hf < 2; hf++) {
#pragma unroll
                for (int t = 0; t < 8; t++) {
                    const int n0 = hf * 64 + t * 8;
                    // B fragments: b0 row(k)=c0+tig col(n)=n0+gid; b1 row+4
                    uint2 B0 = Ash[(c0 + tig) * 130 + n0 + gid];
                    uint2 B1 = Ash[(c0 + tig + 4) * 130 + n0 + gid];
                    float* C = acc[hf][t];
                    mma_tf32(C, A0.x, A1.x, A2.x, A3.x, B0.x, B1.x); // hi*hi
                    mma_tf32(C, A0.x, A1.x, A2.x, A3.x, B0.y, B1.y); // Whi*Alo
                    mma_tf32(C, A0.y, A1.y, A2.y, A3.y, B0.x, B1.x); // Wlo*Ahi
                }
            }
        }
    }

    // Epilogue: bias, stores, BN partials.
    const int   rlo = o0 + gid, rhi = o0 + 8 + gid;
    const float blo = bias[rlo], bhi = bias[rhi];
    float slo = 0.f, qlo = 0.f, shi = 0.f, qhi = 0.f;
    float* dlo = yout + (size_t)rlo * PP + pbase;
    float* dhi = yout + (size_t)rhi * PP + pbase;

#pragma unroll
    for (int hf = 0; hf < 2; hf++) {
#pragma unroll
        for (int t = 0; t < 8; t++) {
            const int p = hf * 64 + t * 8 + tig * 2;
            float v0 = acc[hf][t][0] + blo, v1 = acc[hf][t][1] + blo;
            float v2 = acc[hf][t][2] + bhi, v3 = acc[hf][t][3] + bhi;
            *(float2*)(dlo + p) = make_float2(v0, v1);
            *(float2*)(dhi + p) = make_float2(v2, v3);
            slo += v0 + v1;  qlo += v0 * v0 + v1 * v1;
            shi += v2 + v3;  qhi += v2 * v2 + v3 * v3;
        }
    }
    // reduce over tig lanes (same gid -> adjacent lanes, xor 1,2 stays in quad)
#pragma unroll
    for (int d = 1; d <= 2; d <<= 1) {
        slo += __shfl_xor_sync(0xffffffffu, slo, d);
        qlo += __shfl_xor_sync(0xffffffffu, qlo, d);
        shi += __shfl_xor_sync(0xffffffffu, shi, d);
        qhi += __shfl_xor_sync(0xffffffffu, qhi, d);
    }
    if (tig == 0) {
        ps[(size_t)rlo * NBG + blockIdx.x] = slo;
        pq[(size_t)rlo * NBG + blockIdx.x] = qlo;
        ps[(size_t)rhi * NBG + blockIdx.x] = shi;
        pq[(size_t)rhi * NBG + blockIdx.x] = qhi;
    }
}

// ---------------------------------------------------------------------------
// Max over k with final BN affine applied elementwise (proven version).
// ---------------------------------------------------------------------------
__global__ void maxk_kernel(const float* __restrict__ y3,
                            const float* __restrict__ scale,
                            const float* __restrict__ shift,
                            float* __restrict__ out)
{
    const int n = blockIdx.x * blockDim.x + threadIdx.x;
    const int o = blockIdx.y;
    const int b = blockIdx.z;
    const float sc = scale[o], sf = shift[o];
    const float4* base =
        (const float4*)(y3 + (size_t)o * PP + ((size_t)b * NN + n) * KK);
    float m = -FLT_MAX;
#pragma unroll
    for (int q = 0; q < 5; ++q) {
        float4 v = base[q];
        m = fmaxf(m, fmaf(v.x, sc, sf));
        m = fmaxf(m, fmaf(v.y, sc, sf));
        m = fmaxf(m, fmaf(v.z, sc, sf));
        m = fmaxf(m, fmaf(v.w, sc, sf));
    }
    out[((size_t)b * 128 + o) * NN + n] = m;
}

// ---------------------------------------------------------------------------
// Launcher: graph-capturable, allocation-free.
// ---------------------------------------------------------------------------
extern "C" void kernel_launch(void* const* d_in, const int* in_sizes, int n_in,
                              void* d_out, int out_size)
{
    const float* x   = (const float*)d_in[0];
    const float* W1  = (const float*)d_in[1];
    const float* b1  = (const float*)d_in[2];
    const float* g1  = (const float*)d_in[3];
    const float* be1 = (const float*)d_in[4];
    const float* W2  = (const float*)d_in[5];
    const float* b2  = (const float*)d_in[6];
    const float* g2  = (const float*)d_in[7];
    const float* be2 = (const float*)d_in[8];
    const float* W3  = (const float*)d_in[9];
    const float* b3  = (const float*)d_in[10];
    const float* g3  = (const float*)d_in[11];
    const float* be3 = (const float*)d_in[12];
    float* out = (float*)d_out;

    void *y1p, *y2p, *y3p, *idxp, *psp, *pqp;
    void *sc1p, *sh1p, *sc2p, *sh2p, *sc3p, *sh3p;
    cudaGetSymbolAddress(&y1p,  g_y1);
    cudaGetSymbolAddress(&y2p,  g_y2);
    cudaGetSymbolAddress(&y3p,  g_y3);
    cudaGetSymbolAddress(&idxp, g_idx);
    cudaGetSymbolAddress(&psp,  g_ps);
    cudaGetSymbolAddress(&pqp,  g_pq);
    cudaGetSymbolAddress(&sc1p, g_sc1);  cudaGetSymbolAddress(&sh1p, g_sh1);
    cudaGetSymbolAddress(&sc2p, g_sc2);  cudaGetSymbolAddress(&sh2p, g_sh2);
    cudaGetSymbolAddress(&sc3p, g_sc3);  cudaGetSymbolAddress(&sh3p, g_sh3);

    const int smem64  = (64  * 130 + 64 * 130) * 8;   // 133120 B
    const int smem128 = (128 * 130 + 64 * 130) * 8;   // 199680 B
    cudaFuncSetAttribute(knn_warp_kernel,      cudaFuncAttributeMaxDynamicSharedMemorySize, 65536);
    cudaFuncSetAttribute(gemm_mma_kernel<64>,  cudaFuncAttributeMaxDynamicSharedMemorySize, smem64);
    cudaFuncSetAttribute(gemm_mma_kernel<128>, cudaFuncAttributeMaxDynamicSharedMemorySize, smem128);

    // K0: warp-cooperative kNN (REDUX inserts, 16 queries/block)
    knn_warp_kernel<<<dim3(NN / QPB, BB), 512, 65536>>>(x, (int*)idxp);

    // K1: edge features + conv1 (raw) + BN1 partials
    layer1_kernel<<<NB1, 256>>>(x, (const int*)idxp, W1, b1, (float*)y1p,
                                (float*)psp, (float*)pqp);
    reduce_kernel<<<64, 256>>>((const float*)psp, (const float*)pqp, NB1,
                               g1, be1, (float*)sc1p, (float*)sh1p);

    // conv2 on relu(BN1(y1)) + BN2 partials     (launch #4 -> ncu window)
    gemm_mma_kernel<64><<<NBG, 256, smem64>>>((const float*)y1p, W2, b2,
                                              (const float*)sc1p, (const float*)sh1p,
                                              (float*)y2p, (float*)psp, (float*)pqp);
    reduce_kernel<<<128, 256>>>((const float*)psp, (const float*)pqp, NBG,
                                g2, be2, (float*)sc2p, (float*)sh2p);

    // conv3 on relu(BN2(y2)) + BN3 partials
    gemm_mma_kernel<128><<<NBG, 256, smem128>>>((const float*)y2p, W3, b3,
                                                (const float*)sc2p, (const float*)sh2p,
                                                (float*)y3p, (float*)psp, (float*)pqp);
    reduce_kernel<<<128, 256>>>((const float*)psp, (const float*)pqp, NBG,
                                g3, be3, (float*)sc3p, (float*)sh3p);

    // BN3 affine + max over k
    maxk_kernel<<<dim3(NN / 256, 128, BB), 256>>>((const float*)y3p,
                                                  (const float*)sc3p, (const float*)sh3p,
                                                  out);
}

// round 11
// speedup vs baseline: 1.1349x; 1.1349x over previous
#include <cuda_runtime.h>
#include <cfloat>
#include <math.h>
#include <stdint.h>

// Problem constants (fixed shapes from reference)
#define BB 4
#define NN 4096
#define KK 20
#define QPB 16                // kNN queries per block (1 per warp, 512 threads)
#define PP (BB * NN * KK)     // 327680 positions
#define NB1 (PP / 256)        // layer1 blocks = 1280
#define NBG (PP / 64)         // gemm blocks   = 5120 (64-wide p tiles)

// ---------------------------------------------------------------------------
// Scratch in __device__ globals (no allocation allowed in kernel_launch)
// ---------------------------------------------------------------------------
__device__ float g_y1[64  * PP];
__device__ float g_y2[128 * PP];
__device__ float g_y3[128 * PP];
__device__ int   g_idx[BB * NN * KK];
__device__ float g_ps[128 * NBG];
__device__ float g_pq[128 * NBG];
__device__ float g_sc1[64],  g_sh1[64];
__device__ float g_sc2[128], g_sh2[128];
__device__ float g_sc3[128], g_sh3[128];

// Orderable uint key: ascending float order -> ascending unsigned order.
__device__ __forceinline__ unsigned okey(float f) {
    unsigned u = __float_as_uint(f);
    return u ^ (((unsigned)((int)u >> 31)) | 0x80000000u);
}

// tf32 round-to-nearest
__device__ __forceinline__ unsigned tf32_rna(float f) {
    unsigned r;
    asm("cvt.rna.tf32.f32 %0, %1;" : "=r"(r) : "f"(f));
    return r;
}

// m16n8k8 tf32 mma: D += A(16x8 row) * B(8x8 col)   (mapping verified R10)
__device__ __forceinline__ void mma_tf32(float* c,
                                         unsigned a0, unsigned a1,
                                         unsigned a2, unsigned a3,
                                         unsigned b0, unsigned b1) {
    asm("mma.sync.aligned.m16n8k8.row.col.f32.tf32.tf32.f32 "
        "{%0,%1,%2,%3}, {%4,%5,%6,%7}, {%8,%9}, {%0,%1,%2,%3};"
        : "+f"(c[0]), "+f"(c[1]), "+f"(c[2]), "+f"(c[3])
        : "r"(a0), "r"(a1), "r"(a2), "r"(a3), "r"(b0), "r"(b1));
}

// ---------------------------------------------------------------------------
// K0: warp-cooperative exact kNN (k=20), REDUX-based inserts (R9-proven).
// ---------------------------------------------------------------------------
__global__ void __launch_bounds__(512) knn_warp_kernel(
    const float* __restrict__ x, int* __restrict__ idxo)
{
    extern __shared__ float4 pts[];   // 4096 * 16B = 64KB
    const int b = blockIdx.y;
    const float* xb = x + (size_t)b * NN * 3;
    const int tid = threadIdx.x, lane = tid & 31, w = tid >> 5;

    for (int t = tid; t < NN; t += 512) {
        float px = xb[t * 3 + 0], py = xb[t * 3 + 1], pz = xb[t * 3 + 2];
        pts[t] = make_float4(px, py, pz, px * px + py * py + pz * pz);
    }
    __syncthreads();

    const int i = blockIdx.x * QPB + w;
    float4 q = pts[i];
    const float qx = 2.f * q.x, qy = 2.f * q.y, qz = 2.f * q.z;

    unsigned my_k = (lane < KK) ? okey(-FLT_MAX) : okey(FLT_MAX);
    int      my_j = 0x7fff0000 | lane;
    unsigned wkey = okey(-FLT_MAX);

    for (int jc = 0; jc < NN; jc += 32) {
        float4 p = pts[jc + lane];
        float s = fmaf(qx, p.x, fmaf(qy, p.y, fmaf(qz, p.z, -p.w)));
        unsigned k = okey(s);
        unsigned mask = __ballot_sync(0xffffffffu, k > wkey);
        while (mask) {
            const int l = __ffs(mask) - 1;
            mask &= mask - 1;
            const unsigned kc = __shfl_sync(0xffffffffu, k, l);
            if (kc > wkey) {
                const unsigned umin = __reduce_min_sync(0xffffffffu, my_k);
                const bool tied = (my_k == umin);
                const int jmax = __reduce_max_sync(0xffffffffu, tied ? my_j : -1);
                if (tied && my_j == jmax) { my_k = kc; my_j = jc + l; }
                wkey = __reduce_min_sync(0xffffffffu, my_k);
            }
        }
    }

    if (lane < KK)
        idxo[((size_t)b * NN + i) * KK + lane] = my_j;
}

// ---------------------------------------------------------------------------
// K1: edge features -> conv1 (64x6) + BN1 partials (proven version).
// ---------------------------------------------------------------------------
__global__ void __launch_bounds__(256) layer1_kernel(
    const float* __restrict__ x,
    const int* __restrict__ idx,
    const float* __restrict__ W1,
    const float* __restrict__ b1,
    float* __restrict__ y1,
    float* __restrict__ ps,
    float* __restrict__ pq)
{
    __shared__ float Wsh[64 * 6];
    __shared__ float bsh[64];
    __shared__ float s_s[64 * 8];
    __shared__ float s_q[64 * 8];
    for (int t = threadIdx.x; t < 64 * 6; t += blockDim.x) Wsh[t] = W1[t];
    if (threadIdx.x < 64) bsh[threadIdx.x] = b1[threadIdx.x];
    __syncthreads();

    const int tid  = threadIdx.x;
    const int lane = tid & 31;
    const int warp = tid >> 5;
    const int p  = blockIdx.x * 256 + tid;
    const int bn = p / KK;
    const int b  = bn / NN;
    const int j  = idx[p];

    const float* xi = x + (size_t)bn * 3;
    const float* xj = x + ((size_t)b * NN + j) * 3;
    float xi0 = xi[0], xi1 = xi[1], xi2 = xi[2];
    float f0 = xj[0] - xi0, f1 = xj[1] - xi1, f2 = xj[2] - xi2;

#pragma unroll 4
    for (int o = 0; o < 64; ++o) {
        const float* w = Wsh + o * 6;
        float a = bsh[o];
        a = fmaf(w[0], f0, a);
        a = fmaf(w[1], f1, a);
        a = fmaf(w[2], f2, a);
        a = fmaf(w[3], xi0, a);
        a = fmaf(w[4], xi1, a);
        a = fmaf(w[5], xi2, a);
        y1[(size_t)o * PP + p] = a;

        float s = a, q = a * a;
#pragma unroll
        for (int m = 16; m > 0; m >>= 1) {
            s += __shfl_xor_sync(0xffffffffu, s, m);
            q += __shfl_xor_sync(0xffffffffu, q, m);
        }
        if (lane == 0) { s_s[o * 8 + warp] = s; s_q[o * 8 + warp] = q; }
    }
    __syncthreads();

    if (tid < 64) {
        float acc = 0.f;
#pragma unroll
        for (int w = 0; w < 8; w++) acc += s_s[tid * 8 + w];
        ps[tid * NB1 + blockIdx.x] = acc;
    } else if (tid < 128) {
        const int o = tid - 64;
        float acc = 0.f;
#pragma unroll
        for (int w = 0; w < 8; w++) acc += s_q[o * 8 + w];
        pq[o * NB1 + blockIdx.x] = acc;
    }
}

// ---------------------------------------------------------------------------
// Reduce per-block partials -> fused BN affine (scale, shift).
// ---------------------------------------------------------------------------
__global__ void reduce_kernel(const float* __restrict__ ps,
                              const float* __restrict__ pq,
                              int nb,
                              const float* __restrict__ gamma,
                              const float* __restrict__ beta,
                              float* __restrict__ scale,
                              float* __restrict__ shift)
{
    const int c = blockIdx.x;
    double s = 0.0, q = 0.0;
    for (int i = threadIdx.x; i < nb; i += 256) {
        s += (double)ps[c * nb + i];
        q += (double)pq[c * nb + i];
    }
    __shared__ double r1[256], r2[256];
    r1[threadIdx.x] = s; r2[threadIdx.x] = q;
    __syncthreads();
    for (int off = 128; off > 0; off >>= 1) {
        if (threadIdx.x < off) {
            r1[threadIdx.x] += r1[threadIdx.x + off];
            r2[threadIdx.x] += r2[threadIdx.x + off];
        }
        __syncthreads();
    }
    if (threadIdx.x == 0) {
        double mean = r1[0] / (double)PP;
        double var  = r2[0] / (double)PP - mean * mean;
        double inv  = (double)gamma[c] / sqrt(var + 1e-5);
        scale[c] = (float)inv;
        shift[c] = (float)((double)beta[c] - mean * inv);
    }
}

// ---------------------------------------------------------------------------
// GEMM via mma.sync m16n8k8 tf32, 3xTF32 split (numerics verified R10).
// v2 tiling: 128o x 64p tiles, W AND A staged in 64-deep k-chunks
// -> smem 100KB -> 2 blocks/SM (16 warps). Strides pad ≡ 4 (mod 16) uint2
// (W:132, A:68) give conflict-free LDS.64 per 16-lane phase.
// Warp w: o-rows [16w,16w+16), p 0..64. Epilogue: stores + BN partials.
// ---------------------------------------------------------------------------
template <int CIN>
__global__ void __launch_bounds__(256) gemm_mma_kernel(
    const float* __restrict__ yin,
    const float* __restrict__ W,
    const float* __restrict__ bias,
    const float* __restrict__ scale,
    const float* __restrict__ shift,
    float* __restrict__ yout,
    float* __restrict__ ps,
    float* __restrict__ pq)
{
    extern __shared__ uint2 sh2[];
    uint2* W2  = sh2;                 // [64][132] (hi,lo) of W[o][c] chunk, [c][o]
    uint2* Ash = sh2 + 64 * 132;      // [64][68]  (hi,lo) of activations [c][p]
    const int tid  = threadIdx.x;
    const int lane = tid & 31;
    const int warp = tid >> 5;
    const int gid  = lane >> 2;       // 0..7
    const int tig  = lane & 3;        // 0..3
    const int o0   = warp * 16;
    const int pbase = blockIdx.x * 64;

    float acc[8][4];
#pragma unroll
    for (int t = 0; t < 8; t++)
#pragma unroll
        for (int r = 0; r < 4; r++) acc[t][r] = 0.f;

#pragma unroll
    for (int kc = 0; kc < CIN / 64; ++kc) {
        if (kc > 0) __syncthreads();   // protect previous chunk
        // Stage W chunk: c in [kc*64, kc*64+64), all 128 o
        for (int t = tid; t < 128 * 64; t += 256) {
            int o = t >> 6, c = t & 63;
            float v = W[o * CIN + kc * 64 + c];
            unsigned h = tf32_rna(v);
            unsigned l = tf32_rna(v - __uint_as_float(h));
            W2[c * 132 + o] = make_uint2(h, l);
        }
        // Stage A chunk: 64 c x 64 p, affine+relu+split
        for (int t = tid; t < 64 * 64; t += 256) {
            int c = t >> 6, p = t & 63;
            int cg = kc * 64 + c;
            float v = fmaxf(fmaf(yin[(size_t)cg * PP + pbase + p],
                                 scale[cg], shift[cg]), 0.f);
            unsigned h = tf32_rna(v);
            unsigned l = tf32_rna(v - __uint_as_float(h));
            Ash[c * 68 + p] = make_uint2(h, l);
        }
        __syncthreads();

#pragma unroll
        for (int ks = 0; ks < 8; ++ks) {
            const int c0 = ks * 8;
            // A fragments (W): row=o, col=k (within chunk)
            uint2 A0 = W2[(c0 + tig) * 132 + o0 + gid];
            uint2 A1 = W2[(c0 + tig) * 132 + o0 + gid + 8];
            uint2 A2 = W2[(c0 + tig + 4) * 132 + o0 + gid];
            uint2 A3 = W2[(c0 + tig + 4) * 132 + o0 + gid + 8];
#pragma unroll
            for (int t = 0; t < 8; t++) {
                const int n0 = t * 8;
                uint2 B0 = Ash[(c0 + tig) * 68 + n0 + gid];
                uint2 B1 = Ash[(c0 + tig + 4) * 68 + n0 + gid];
                float* C = acc[t];
                mma_tf32(C, A0.x, A1.x, A2.x, A3.x, B0.x, B1.x); // hi*hi
                mma_tf32(C, A0.x, A1.x, A2.x, A3.x, B0.y, B1.y); // Whi*Alo
                mma_tf32(C, A0.y, A1.y, A2.y, A3.y, B0.x, B1.x); // Wlo*Ahi
            }
        }
    }

    // Epilogue: bias, stores, BN partials.
    const int   rlo = o0 + gid, rhi = o0 + 8 + gid;
    const float blo = bias[rlo], bhi = bias[rhi];
    float slo = 0.f, qlo = 0.f, shi = 0.f, qhi = 0.f;
    float* dlo = yout + (size_t)rlo * PP + pbase;
    float* dhi = yout + (size_t)rhi * PP + pbase;

#pragma unroll
    for (int t = 0; t < 8; t++) {
        const int p = t * 8 + tig * 2;
        float v0 = acc[t][0] + blo, v1 = acc[t][1] + blo;
        float v2 = acc[t][2] + bhi, v3 = acc[t][3] + bhi;
        *(float2*)(dlo + p) = make_float2(v0, v1);
        *(float2*)(dhi + p) = make_float2(v2, v3);
        slo += v0 + v1;  qlo += v0 * v0 + v1 * v1;
        shi += v2 + v3;  qhi += v2 * v2 + v3 * v3;
    }
#pragma unroll
    for (int d = 1; d <= 2; d <<= 1) {
        slo += __shfl_xor_sync(0xffffffffu, slo, d);
        qlo += __shfl_xor_sync(0xffffffffu, qlo, d);
        shi += __shfl_xor_sync(0xffffffffu, shi, d);
        qhi += __shfl_xor_sync(0xffffffffu, qhi, d);
    }
    if (tig == 0) {
        ps[(size_t)rlo * NBG + blockIdx.x] = slo;
        pq[(size_t)rlo * NBG + blockIdx.x] = qlo;
        ps[(size_t)rhi * NBG + blockIdx.x] = shi;
        pq[(size_t)rhi * NBG + blockIdx.x] = qhi;
    }
}

// ---------------------------------------------------------------------------
// Max over k with final BN affine applied elementwise (proven version).
// ---------------------------------------------------------------------------
__global__ void maxk_kernel(const float* __restrict__ y3,
                            const float* __restrict__ scale,
                            const float* __restrict__ shift,
                            float* __restrict__ out)
{
    const int n = blockIdx.x * blockDim.x + threadIdx.x;
    const int o = blockIdx.y;
    const int b = blockIdx.z;
    const float sc = scale[o], sf = shift[o];
    const float4* base =
        (const float4*)(y3 + (size_t)o * PP + ((size_t)b * NN + n) * KK);
    float m = -FLT_MAX;
#pragma unroll
    for (int q = 0; q < 5; ++q) {
        float4 v = base[q];
        m = fmaxf(m, fmaf(v.x, sc, sf));
        m = fmaxf(m, fmaf(v.y, sc, sf));
        m = fmaxf(m, fmaf(v.z, sc, sf));
        m = fmaxf(m, fmaf(v.w, sc, sf));
    }
    out[((size_t)b * 128 + o) * NN + n] = m;
}

// ---------------------------------------------------------------------------
// Launcher: graph-capturable, allocation-free.
// ---------------------------------------------------------------------------
extern "C" void kernel_launch(void* const* d_in, const int* in_sizes, int n_in,
                              void* d_out, int out_size)
{
    const float* x   = (const float*)d_in[0];
    const float* W1  = (const float*)d_in[1];
    const float* b1  = (const float*)d_in[2];
    const float* g1  = (const float*)d_in[3];
    const float* be1 = (const float*)d_in[4];
    const float* W2  = (const float*)d_in[5];
    const float* b2  = (const float*)d_in[6];
    const float* g2  = (const float*)d_in[7];
    const float* be2 = (const float*)d_in[8];
    const float* W3  = (const float*)d_in[9];
    const float* b3  = (const float*)d_in[10];
    const float* g3  = (const float*)d_in[11];
    const float* be3 = (const float*)d_in[12];
    float* out = (float*)d_out;

    void *y1p, *y2p, *y3p, *idxp, *psp, *pqp;
    void *sc1p, *sh1p, *sc2p, *sh2p, *sc3p, *sh3p;
    cudaGetSymbolAddress(&y1p,  g_y1);
    cudaGetSymbolAddress(&y2p,  g_y2);
    cudaGetSymbolAddress(&y3p,  g_y3);
    cudaGetSymbolAddress(&idxp, g_idx);
    cudaGetSymbolAddress(&psp,  g_ps);
    cudaGetSymbolAddress(&pqp,  g_pq);
    cudaGetSymbolAddress(&sc1p, g_sc1);  cudaGetSymbolAddress(&sh1p, g_sh1);
    cudaGetSymbolAddress(&sc2p, g_sc2);  cudaGetSymbolAddress(&sh2p, g_sh2);
    cudaGetSymbolAddress(&sc3p, g_sc3);  cudaGetSymbolAddress(&sh3p, g_sh3);

    const int smemG = (64 * 132 + 64 * 68) * 8;   // 102400 B -> 2 blocks/SM
    cudaFuncSetAttribute(knn_warp_kernel,      cudaFuncAttributeMaxDynamicSharedMemorySize, 65536);
    cudaFuncSetAttribute(gemm_mma_kernel<64>,  cudaFuncAttributeMaxDynamicSharedMemorySize, smemG);
    cudaFuncSetAttribute(gemm_mma_kernel<128>, cudaFuncAttributeMaxDynamicSharedMemorySize, smemG);

    // K0: warp-cooperative kNN
    knn_warp_kernel<<<dim3(NN / QPB, BB), 512, 65536>>>(x, (int*)idxp);

    // K1: edge features + conv1 (raw) + BN1 partials
    layer1_kernel<<<NB1, 256>>>(x, (const int*)idxp, W1, b1, (float*)y1p,
                                (float*)psp, (float*)pqp);
    reduce_kernel<<<64, 256>>>((const float*)psp, (const float*)pqp, NB1,
                               g1, be1, (float*)sc1p, (float*)sh1p);

    // conv2 on relu(BN1(y1)) + BN2 partials     (launch #4 -> ncu window)
    gemm_mma_kernel<64><<<NBG, 256, smemG>>>((const float*)y1p, W2, b2,
                                             (const float*)sc1p, (const float*)sh1p,
                                             (float*)y2p, (float*)psp, (float*)pqp);
    reduce_kernel<<<128, 256>>>((const float*)psp, (const float*)pqp, NBG,
                                g2, be2, (float*)sc2p, (float*)sh2p);

    // conv3 on relu(BN2(y2)) + BN3 partials
    gemm_mma_kernel<128><<<NBG, 256, smemG>>>((const float*)y2p, W3, b3,
                                              (const float*)sc2p, (const float*)sh2p,
                                              (float*)y3p, (float*)psp, (float*)pqp);
    reduce_kernel<<<128, 256>>>((const float*)psp, (const float*)pqp, NBG,
                                g3, be3, (float*)sc3p, (float*)sh3p);

    // BN3 affine + max over k
    maxk_kernel<<<dim3(NN / 256, 128, BB), 256>>>((const float*)y3p,
                                                  (const float*)sc3p, (const float*)sh3p,
                                                  out);
}

// round 13
// speedup vs baseline: 1.3858x; 1.2211x over previous
#include <cuda_runtime.h>
#include <cfloat>
#include <math.h>
#include <stdint.h>

// Problem constants (fixed shapes from reference)
#define BB 4
#define NN 4096
#define KK 20
#define QPB 16                // kNN queries per block (1 per warp, 512 threads)
#define PP (BB * NN * KK)     // 327680 positions
#define NB1 (PP / 256)        // stats1 blocks = 1280
#define NBG (PP / 128)        // gemm blocks   = 2560

// ---------------------------------------------------------------------------
// Scratch in __device__ globals (no allocation allowed in kernel_launch)
// ---------------------------------------------------------------------------
__device__ float g_y2[128 * PP];
__device__ float g_y3[128 * PP];
__device__ int   g_idx[BB * NN * KK];
__device__ float g_ps[128 * NBG];     // BN partials (also reused for f-moments)
__device__ float g_pq[128 * NBG];
__device__ float g_sc1[64],  g_sh1[64];
__device__ float g_sc2[128], g_sh2[128];
__device__ float g_sc3[128], g_sh3[128];

// ---------------------------------------------------------------------------
// Packed fp32x2 helpers (FFMA2)
// ---------------------------------------------------------------------------
__device__ __forceinline__ unsigned long long splat2(float v) {
    unsigned long long r;
    asm("mov.b64 %0, {%1, %1};" : "=l"(r) : "f"(v));
    return r;
}
__device__ __forceinline__ void ffma2(unsigned long long& d,
                                      unsigned long long a,
                                      unsigned long long b) {
    asm("fma.rn.f32x2 %0, %1, %2, %0;" : "+l"(d) : "l"(a), "l"(b));
}
__device__ __forceinline__ float2 unpack2(unsigned long long v) {
    float2 f;
    asm("mov.b64 {%0, %1}, %2;" : "=f"(f.x), "=f"(f.y) : "l"(v));
    return f;
}

// Orderable uint key: ascending float order -> ascending unsigned order.
__device__ __forceinline__ unsigned okey(float f) {
    unsigned u = __float_as_uint(f);
    return u ^ (((unsigned)((int)u >> 31)) | 0x80000000u);
}

// ---------------------------------------------------------------------------
// K0: warp-cooperative exact kNN (k=20), REDUX inserts with unique-min fast
// path (jmax tie-break reduce only when >1 slot ties the min — warp-uniform).
// Exact top_k semantics preserved (ascending-j scan, strict >, evict
// (min s, largest j)).
// ---------------------------------------------------------------------------
__global__ void __launch_bounds__(512) knn_warp_kernel(
    const float* __restrict__ x, int* __restrict__ idxo)
{
    extern __shared__ float4 pts[];
    const int b = blockIdx.y;
    const float* xb = x + (size_t)b * NN * 3;
    const int tid = threadIdx.x, lane = tid & 31, w = tid >> 5;

    for (int t = tid; t < NN; t += 512) {
        float px = xb[t * 3 + 0], py = xb[t * 3 + 1], pz = xb[t * 3 + 2];
        pts[t] = make_float4(px, py, pz, px * px + py * py + pz * pz);
    }
    __syncthreads();

    const int i = blockIdx.x * QPB + w;
    float4 q = pts[i];
    const float qx = 2.f * q.x, qy = 2.f * q.y, qz = 2.f * q.z;

    unsigned my_k = (lane < KK) ? okey(-FLT_MAX) : okey(FLT_MAX);
    int      my_j = 0x7fff0000 | lane;
    unsigned wkey = okey(-FLT_MAX);

    for (int jc = 0; jc < NN; jc += 32) {
        float4 p = pts[jc + lane];
        float s = fmaf(qx, p.x, fmaf(qy, p.y, fmaf(qz, p.z, -p.w)));
        unsigned k = okey(s);
        unsigned mask = __ballot_sync(0xffffffffu, k > wkey);
        while (mask) {
            const int l = __ffs(mask) - 1;
            mask &= mask - 1;
            const unsigned kc = __shfl_sync(0xffffffffu, k, l);
            if (kc > wkey) {
                const unsigned umin = __reduce_min_sync(0xffffffffu, my_k);
                unsigned em = __ballot_sync(0xffffffffu, my_k == umin);
                if (__popc(em) > 1) {   // rare after warm-up
                    const bool tied = (my_k == umin);
                    const int jmax = __reduce_max_sync(0xffffffffu, tied ? my_j : -1);
                    em = __ballot_sync(0xffffffffu, tied && my_j == jmax);
                }
                if (lane == __ffs(em) - 1) { my_k = kc; my_j = jc + l; }
                wkey = __reduce_min_sync(0xffffffffu, my_k);
            }
        }
    }

    if (lane < KK)
        idxo[((size_t)b * NN + i) * KK + lane] = my_j;
}

// ---------------------------------------------------------------------------
// stats1: accumulate f-moments over all P positions.
// f = (xj-xi, xi) (6 vals). Outputs 27 block-partials: S[0..5], M upper-tri
// indexed base(d)=6+6d-d(d-1)/2, idx(d,e)=base(d)+(e-d).
// ---------------------------------------------------------------------------
__global__ void __launch_bounds__(256) stats1_kernel(
    const float* __restrict__ x, const int* __restrict__ idx,
    float* __restrict__ pf)
{
    const int tid  = threadIdx.x;
    const int lane = tid & 31;
    const int warp = tid >> 5;
    const int p  = blockIdx.x * 256 + tid;
    const int bn = p / KK;
    const int b  = bn >> 12;
    const int j  = idx[p];

    const float* xi = x + (size_t)bn * 3;
    const float* xj = x + ((size_t)b * NN + j) * 3;
    float f[6];
    f[3] = xi[0]; f[4] = xi[1]; f[5] = xi[2];
    f[0] = xj[0] - f[3]; f[1] = xj[1] - f[4]; f[2] = xj[2] - f[5];

    float acc[27];
#pragma unroll
    for (int d = 0; d < 6; d++) acc[d] = f[d];
    {
        int k = 6;
#pragma unroll
        for (int d = 0; d < 6; d++)
#pragma unroll
            for (int e = d; e < 6; e++) acc[k++] = f[d] * f[e];
    }

    __shared__ float s_m[27 * 8];
#pragma unroll
    for (int s = 0; s < 27; s++) {
        float v = acc[s];
#pragma unroll
        for (int m = 16; m > 0; m >>= 1)
            v += __shfl_xor_sync(0xffffffffu, v, m);
        if (lane == 0) s_m[s * 8 + warp] = v;
    }
    __syncthreads();

    if (tid < 27) {
        float a = 0.f;
#pragma unroll
        for (int w = 0; w < 8; w++) a += s_m[tid * 8 + w];
        pf[tid * NB1 + blockIdx.x] = a;
    }
}

// ---------------------------------------------------------------------------
// affine1: reduce f-moments -> analytic BN1 affine per channel.
// mean = (w.S)/P + b;  E2 = (w'Mw + 2b w.S)/P + b^2;  var = E2 - mean^2.
// ---------------------------------------------------------------------------
__global__ void affine1_kernel(const float* __restrict__ pf,
                               const float* __restrict__ W1,
                               const float* __restrict__ b1,
                               const float* __restrict__ g1,
                               const float* __restrict__ be1,
                               float* __restrict__ sc,
                               float* __restrict__ sh)
{
    __shared__ double red[256];
    __shared__ double st[27];
    for (int s = 0; s < 27; ++s) {
        double a = 0.0;
        for (int i = threadIdx.x; i < NB1; i += 256)
            a += (double)pf[s * NB1 + i];
        red[threadIdx.x] = a;
        __syncthreads();
        for (int off = 128; off > 0; off >>= 1) {
            if (threadIdx.x < off) red[threadIdx.x] += red[threadIdx.x + off];
            __syncthreads();
        }
        if (threadIdx.x == 0) st[s] = red[0];
        __syncthreads();
    }
    if (threadIdx.x < 64) {
        const int c = threadIdx.x;
        double w[6];
#pragma unroll
        for (int d = 0; d < 6; d++) w[d] = (double)W1[c * 6 + d];
        const double b = (double)b1[c];
        double ws = 0.0;
#pragma unroll
        for (int d = 0; d < 6; d++) ws += w[d] * st[d];
        double wmw = 0.0;
        int k = 6;
#pragma unroll
        for (int d = 0; d < 6; d++)
#pragma unroll
            for (int e = d; e < 6; e++, k++)
                wmw += ((d == e) ? w[d] * w[d] : 2.0 * w[d] * w[e]) * st[k];
        const double Pd = (double)PP;
        double mean = ws / Pd + b;
        double e2   = (wmw + 2.0 * b * ws) / Pd + b * b;
        double var  = e2 - mean * mean;
        double inv  = (double)g1[c] / sqrt(var + 1e-5);
        sc[c] = (float)inv;
        sh[c] = (float)((double)be1[c] - mean * inv);
    }
}

// ---------------------------------------------------------------------------
// Reduce per-block partials -> fused BN affine (BN2/BN3; proven).
// ---------------------------------------------------------------------------
__global__ void reduce_kernel(const float* __restrict__ ps,
                              const float* __restrict__ pq, int nb,
                              const float* __restrict__ gamma,
                              const float* __restrict__ beta,
                              float* __restrict__ scale,
                              float* __restrict__ shift)
{
    const int c = blockIdx.x;
    double s = 0.0, q = 0.0;
    for (int i = threadIdx.x; i < nb; i += 256) {
        s += (double)ps[c * nb + i];
        q += (double)pq[c * nb + i];
    }
    __shared__ double r1[256], r2[256];
    r1[threadIdx.x] = s; r2[threadIdx.x] = q;
    __syncthreads();
    for (int off = 128; off > 0; off >>= 1) {
        if (threadIdx.x < off) {
            r1[threadIdx.x] += r1[threadIdx.x + off];
            r2[threadIdx.x] += r2[threadIdx.x + off];
        }
        __syncthreads();
    }
    if (threadIdx.x == 0) {
        double mean = r1[0] / (double)PP;
        double var  = r2[0] / (double)PP - mean * mean;
        double inv  = (double)gamma[c] / sqrt(var + 1e-5);
        scale[c] = (float)inv;
        shift[c] = (float)((double)beta[c] - mean * inv);
    }
}

// ---------------------------------------------------------------------------
// Fused conv1+BN1+relu+conv2 GEMM (CIN=64), FFMA2 inner loop (proven shape).
// Staging computes conv1 on the fly from a smem f-tile (y1 never stored):
//   phase A: 128 positions -> f[6] each (gathers via idx)
//   phase B: Ash[c][p] = relu(sc1[c]*(W1[c].f[p]+b1[c])+sh1[c])
// Mainloop/epilogue identical to the proven 651us gemm64.
// ---------------------------------------------------------------------------
__global__ void __launch_bounds__(256, 2) gemm_fused_kernel(
    const float* __restrict__ x,
    const int* __restrict__ idx,
    const float* __restrict__ W1,
    const float* __restrict__ b1,
    const float* __restrict__ sc1,
    const float* __restrict__ sh1,
    const float* __restrict__ W,     // W2 [128][64]
    const float* __restrict__ bias,  // b2
    float* __restrict__ yout,
    float* __restrict__ ps,
    float* __restrict__ pq)
{
    extern __shared__ float sh[];
    float* Wsh   = sh;                     // [64][132] transposed W2
    float* Ash   = Wsh + 64 * 132;         // [64][128]
    float* fs    = Ash + 64 * 128;         // [128][7] (stride-7: conflict-free)
    float* W1sh  = fs + 128 * 7;           // [64][6]
    float* b1sh  = W1sh + 64 * 6;          // [64]
    float* sc1sh = b1sh + 64;              // [64]
    float* sh1sh = sc1sh + 64;             // [64]
    const int tid = threadIdx.x;

    for (int t = tid; t < 128 * 64; t += 256) {
        int o = t >> 6, c = t & 63;
        Wsh[c * 132 + o] = W[t];
    }
    for (int t = tid; t < 64 * 6; t += 256) W1sh[t] = W1[t];
    if (tid < 64) {
        b1sh[tid]  = b1[tid];
        sc1sh[tid] = sc1[tid];
        sh1sh[tid] = sh1[tid];
    }

    const int pbase = blockIdx.x * 128;
    // phase A: edge features for this tile's 128 positions
    if (tid < 128) {
        const int p  = pbase + tid;
        const int bn = p / KK;
        const int b  = bn >> 12;
        const int j  = idx[p];
        const float* xi = x + (size_t)bn * 3;
        const float* xj = x + ((size_t)b * NN + j) * 3;
        float xi0 = xi[0], xi1 = xi[1], xi2 = xi[2];
        fs[tid * 7 + 0] = xj[0] - xi0;
        fs[tid * 7 + 1] = xj[1] - xi1;
        fs[tid * 7 + 2] = xj[2] - xi2;
        fs[tid * 7 + 3] = xi0;
        fs[tid * 7 + 4] = xi1;
        fs[tid * 7 + 5] = xi2;
    }
    __syncthreads();

    // phase B: conv1 + BN1 affine + relu into Ash
    for (int t = tid; t < 64 * 128; t += 256) {
        int c = t >> 7, p = t & 127;
        const float* w = W1sh + c * 6;
        const float* f = fs + p * 7;
        float a = b1sh[c];
        a = fmaf(w[0], f[0], a);
        a = fmaf(w[1], f[1], a);
        a = fmaf(w[2], f[2], a);
        a = fmaf(w[3], f[3], a);
        a = fmaf(w[4], f[4], a);
        a = fmaf(w[5], f[5], a);
        Ash[t] = fmaxf(fmaf(a, sc1sh[c], sh1sh[c]), 0.f);
    }
    __syncthreads();

    const int tx = tid & 15;
    const int ty = tid >> 4;

    unsigned long long acc[8][4];
#pragma unroll
    for (int i = 0; i < 8; i++)
#pragma unroll
        for (int jp = 0; jp < 4; jp++) acc[i][jp] = 0ULL;

#pragma unroll 4
    for (int c = 0; c < 64; ++c) {
        ulonglong2 A0 = *(const ulonglong2*)(Ash + c * 128 + tx * 4);
        ulonglong2 A1 = *(const ulonglong2*)(Ash + c * 128 + 64 + tx * 4);
        unsigned long long av[4] = {A0.x, A0.y, A1.x, A1.y};
        float4 w0 = *(const float4*)(Wsh + c * 132 + ty * 4);
        float4 w1 = *(const float4*)(Wsh + c * 132 + 64 + ty * 4);
        float wf[8] = {w0.x, w0.y, w0.z, w0.w, w1.x, w1.y, w1.z, w1.w};
#pragma unroll
        for (int i = 0; i < 8; i++) {
            unsigned long long wsp = splat2(wf[i]);
#pragma unroll
            for (int jp = 0; jp < 4; jp++) ffma2(acc[i][jp], wsp, av[jp]);
        }
    }

#pragma unroll
    for (int i = 0; i < 8; i++) {
        const int o = (i < 4) ? (ty * 4 + i) : (64 + ty * 4 + (i - 4));
        const float bo = bias[o];
        float2 p0 = unpack2(acc[i][0]);
        float2 p1 = unpack2(acc[i][1]);
        float2 p2 = unpack2(acc[i][2]);
        float2 p3 = unpack2(acc[i][3]);
        float v0 = p0.x + bo, v1 = p0.y + bo, v2 = p1.x + bo, v3 = p1.y + bo;
        float v4 = p2.x + bo, v5 = p2.y + bo, v6 = p3.x + bo, v7 = p3.y + bo;
        float* dst = yout + (size_t)o * PP + pbase;
        *(float4*)(dst + tx * 4)      = make_float4(v0, v1, v2, v3);
        *(float4*)(dst + 64 + tx * 4) = make_float4(v4, v5, v6, v7);

        float s = v0 + v1 + v2 + v3 + v4 + v5 + v6 + v7;
        float q = v0 * v0 + v1 * v1 + v2 * v2 + v3 * v3
                + v4 * v4 + v5 * v5 + v6 * v6 + v7 * v7;
#pragma unroll
        for (int m = 8; m > 0; m >>= 1) {
            s += __shfl_xor_sync(0xffffffffu, s, m, 16);
            q += __shfl_xor_sync(0xffffffffu, q, m, 16);
        }
        if (tx == 0) {
            ps[(size_t)o * NBG + blockIdx.x] = s;
            pq[(size_t)o * NBG + blockIdx.x] = q;
        }
    }
}

// ---------------------------------------------------------------------------
// GEMM (proven): FFMA2 inner loop, 64-deep k-chunks, 2 blocks/SM. CIN=128.
// ---------------------------------------------------------------------------
template <int CIN>
__global__ void __launch_bounds__(256, 2) gemm_kernel(
    const float* __restrict__ yin,
    const float* __restrict__ W,
    const float* __restrict__ bias,
    const float* __restrict__ scale,
    const float* __restrict__ shift,
    float* __restrict__ yout,
    float* __restrict__ ps,
    float* __restrict__ pq)
{
    extern __shared__ float sh[];
    float* Wsh = sh;                  // transposed [CIN][132]
    float* Ash = sh + 132 * CIN;      // [64][128] k-chunk
    const int tid = threadIdx.x;

    for (int t = tid; t < 128 * CIN; t += 256) {
        int o = t / CIN, c = t - o * CIN;
        Wsh[c * 132 + o] = W[t];
    }

    const int pbase = blockIdx.x * 128;
    const int tx = tid & 15;
    const int ty = tid >> 4;

    unsigned long long acc[8][4];
#pragma unroll
    for (int i = 0; i < 8; i++)
#pragma unroll
        for (int jp = 0; jp < 4; jp++) acc[i][jp] = 0ULL;

#pragma unroll
    for (int kc = 0; kc < CIN / 64; ++kc) {
        __syncthreads();
        for (int t = tid; t < 64 * 128; t += 256) {
            int c = t >> 7, p = t & 127;
            int cg = kc * 64 + c;
            float v = yin[(size_t)cg * PP + pbase + p];
            v = fmaf(v, scale[cg], shift[cg]);
            Ash[t] = fmaxf(v, 0.f);
        }
        __syncthreads();

#pragma unroll 4
        for (int c = 0; c < 64; ++c) {
            const int cg = kc * 64 + c;
            ulonglong2 A0 = *(const ulonglong2*)(Ash + c * 128 + tx * 4);
            ulonglong2 A1 = *(const ulonglong2*)(Ash + c * 128 + 64 + tx * 4);
            unsigned long long av[4] = {A0.x, A0.y, A1.x, A1.y};
            float4 w0 = *(const float4*)(Wsh + cg * 132 + ty * 4);
            float4 w1 = *(const float4*)(Wsh + cg * 132 + 64 + ty * 4);
            float wf[8] = {w0.x, w0.y, w0.z, w0.w, w1.x, w1.y, w1.z, w1.w};
#pragma unroll
            for (int i = 0; i < 8; i++) {
                unsigned long long wsp = splat2(wf[i]);
#pragma unroll
                for (int jp = 0; jp < 4; jp++) ffma2(acc[i][jp], wsp, av[jp]);
            }
        }
    }

#pragma unroll
    for (int i = 0; i < 8; i++) {
        const int o = (i < 4) ? (ty * 4 + i) : (64 + ty * 4 + (i - 4));
        const float bo = bias[o];
        float2 p0 = unpack2(acc[i][0]);
        float2 p1 = unpack2(acc[i][1]);
        float2 p2 = unpack2(acc[i][2]);
        float2 p3 = unpack2(acc[i][3]);
        float v0 = p0.x + bo, v1 = p0.y + bo, v2 = p1.x + bo, v3 = p1.y + bo;
        float v4 = p2.x + bo, v5 = p2.y + bo, v6 = p3.x + bo, v7 = p3.y + bo;
        float* dst = yout + (size_t)o * PP + pbase;
        *(float4*)(dst + tx * 4)      = make_float4(v0, v1, v2, v3);
        *(float4*)(dst + 64 + tx * 4) = make_float4(v4, v5, v6, v7);

        float s = v0 + v1 + v2 + v3 + v4 + v5 + v6 + v7;
        float q = v0 * v0 + v1 * v1 + v2 * v2 + v3 * v3
                + v4 * v4 + v5 * v5 + v6 * v6 + v7 * v7;
#pragma unroll
        for (int m = 8; m > 0; m >>= 1) {
            s += __shfl_xor_sync(0xffffffffu, s, m, 16);
            q += __shfl_xor_sync(0xffffffffu, q, m, 16);
        }
        if (tx == 0) {
            ps[(size_t)o * NBG + blockIdx.x] = s;
            pq[(size_t)o * NBG + blockIdx.x] = q;
        }
    }
}

// ---------------------------------------------------------------------------
// Max over k with final BN affine applied elementwise (proven).
// ---------------------------------------------------------------------------
__global__ void maxk_kernel(const float* __restrict__ y3,
                            const float* __restrict__ scale,
                            const float* __restrict__ shift,
                            float* __restrict__ out)
{
    const int n = blockIdx.x * blockDim.x + threadIdx.x;
    const int o = blockIdx.y;
    const int b = blockIdx.z;
    const float sc = scale[o], sf = shift[o];
    const float4* base =
        (const float4*)(y3 + (size_t)o * PP + ((size_t)b * NN + n) * KK);
    float m = -FLT_MAX;
#pragma unroll
    for (int q = 0; q < 5; ++q) {
        float4 v = base[q];
        m = fmaxf(m, fmaf(v.x, sc, sf));
        m = fmaxf(m, fmaf(v.y, sc, sf));
        m = fmaxf(m, fmaf(v.z, sc, sf));
        m = fmaxf(m, fmaf(v.w, sc, sf));
    }
    out[((size_t)b * 128 + o) * NN + n] = m;
}

// ---------------------------------------------------------------------------
// Launcher: graph-capturable, allocation-free.
// ---------------------------------------------------------------------------
extern "C" void kernel_launch(void* const* d_in, const int* in_sizes, int n_in,
                              void* d_out, int out_size)
{
    const float* x   = (const float*)d_in[0];
    const float* W1  = (const float*)d_in[1];
    const float* b1  = (const float*)d_in[2];
    const float* g1  = (const float*)d_in[3];
    const float* be1 = (const float*)d_in[4];
    const float* W2  = (const float*)d_in[5];
    const float* b2  = (const float*)d_in[6];
    const float* g2  = (const float*)d_in[7];
    const float* be2 = (const float*)d_in[8];
    const float* W3  = (const float*)d_in[9];
    const float* b3  = (const float*)d_in[10];
    const float* g3  = (const float*)d_in[11];
    const float* be3 = (const float*)d_in[12];
    float* out = (float*)d_out;

    void *y2p, *y3p, *idxp, *psp, *pqp;
    void *sc1p, *sh1p, *sc2p, *sh2p, *sc3p, *sh3p;
    cudaGetSymbolAddress(&y2p,  g_y2);
    cudaGetSymbolAddress(&y3p,  g_y3);
    cudaGetSymbolAddress(&idxp, g_idx);
    cudaGetSymbolAddress(&psp,  g_ps);
    cudaGetSymbolAddress(&pqp,  g_pq);
    cudaGetSymbolAddress(&sc1p, g_sc1);  cudaGetSymbolAddress(&sh1p, g_sh1);
    cudaGetSymbolAddress(&sc2p, g_sc2);  cudaGetSymbolAddress(&sh2p, g_sh2);
    cudaGetSymbolAddress(&sc3p, g_sc3);  cudaGetSymbolAddress(&sh3p, g_sh3);

    const int smemF   = (64 * 132 + 64 * 128 + 128 * 7 + 64 * 6 + 3 * 64) * 4; // 72448
    const int smem128 = (132 * 128 + 64 * 128) * 4;                             // 100352
    cudaFuncSetAttribute(knn_warp_kernel,  cudaFuncAttributeMaxDynamicSharedMemorySize, 65536);
    cudaFuncSetAttribute(gemm_fused_kernel,cudaFuncAttributeMaxDynamicSharedMemorySize, smemF);
    cudaFuncSetAttribute(gemm_kernel<128>, cudaFuncAttributeMaxDynamicSharedMemorySize, smem128);

    // K0: warp-cooperative kNN
    knn_warp_kernel<<<dim3(NN / QPB, BB), 512, 65536>>>(x, (int*)idxp);

    // BN1 via f-moments (analytic; y1 never materialized)
    stats1_kernel<<<NB1, 256>>>(x, (const int*)idxp, (float*)psp);
    affine1_kernel<<<1, 256>>>((const float*)psp, W1, b1, g1, be1,
                               (float*)sc1p, (float*)sh1p);

    // conv1+BN1+relu+conv2 fused + BN2 partials   (launch #4 -> ncu window)
    gemm_fused_kernel<<<NBG, 256, smemF>>>(x, (const int*)idxp, W1, b1,
                                           (const float*)sc1p, (const float*)sh1p,
                                           W2, b2, (float*)y2p,
                                           (float*)psp, (float*)pqp);
    reduce_kernel<<<128, 256>>>((const float*)psp, (const float*)pqp, NBG,
                                g2, be2, (float*)sc2p, (float*)sh2p);

    // conv3 on relu(BN2(y2)) + BN3 partials
    gemm_kernel<128><<<NBG, 256, smem128>>>((const float*)y2p, W3, b3,
                                            (const float*)sc2p, (const float*)sh2p,
                                            (float*)y3p, (float*)psp, (float*)pqp);
    reduce_kernel<<<128, 256>>>((const float*)psp, (const float*)pqp, NBG,
                                g3, be3, (float*)sc3p, (float*)sh3p);

    // BN3 affine + max over k
    maxk_kernel<<<dim3(NN / 256, 128, BB), 256>>>((const float*)y3p,
                                                  (const float*)sc3p, (const float*)sh3p,
                                                  out);
}

// round 14
// speedup vs baseline: 1.5288x; 1.1032x over previous
#include <cuda_runtime.h>
#include <cfloat>
#include <math.h>
#include <stdint.h>

// Problem constants (fixed shapes from reference)
#define BB 4
#define NN 4096
#define KK 20
#define QPB 16                // kNN queries per block (1 per warp, 512 threads)
#define PP (BB * NN * KK)     // 327680 positions
#define NB1 (PP / 256)        // stats1 blocks = 1280
#define NBG (PP / 128)        // gemm blocks   = 2560

// ---------------------------------------------------------------------------
// Scratch in __device__ globals (no allocation allowed in kernel_launch)
// ---------------------------------------------------------------------------
__device__ float g_y2[128 * PP];
__device__ float g_y3[128 * PP];
__device__ int   g_idx[BB * NN * KK];
__device__ float g_ps[128 * NBG];     // BN partials (reused for f-moments)
__device__ float g_pq[128 * NBG];
__device__ float g_sc1[64],  g_sh1[64];
__device__ float g_sc2[128], g_sh2[128];
__device__ float g_sc3[128], g_sh3[128];

// ---------------------------------------------------------------------------
// Packed fp32x2 helpers (FFMA2)
// ---------------------------------------------------------------------------
__device__ __forceinline__ unsigned long long splat2(float v) {
    unsigned long long r;
    asm("mov.b64 %0, {%1, %1};" : "=l"(r) : "f"(v));
    return r;
}
__device__ __forceinline__ void ffma2(unsigned long long& d,
                                      unsigned long long a,
                                      unsigned long long b) {
    asm("fma.rn.f32x2 %0, %1, %2, %0;" : "+l"(d) : "l"(a), "l"(b));
}
__device__ __forceinline__ float2 unpack2(unsigned long long v) {
    float2 f;
    asm("mov.b64 {%0, %1}, %2;" : "=f"(f.x), "=f"(f.y) : "l"(v));
    return f;
}

// Orderable uint key: ascending float order -> ascending unsigned order.
__device__ __forceinline__ unsigned okey(float f) {
    unsigned u = __float_as_uint(f);
    return u ^ (((unsigned)((int)u >> 31)) | 0x80000000u);
}

// ---------------------------------------------------------------------------
// K0: warp-cooperative exact kNN (k=20), REDUX inserts — R9-proven (92.8us).
// ---------------------------------------------------------------------------
__global__ void __launch_bounds__(512) knn_warp_kernel(
    const float* __restrict__ x, int* __restrict__ idxo)
{
    extern __shared__ float4 pts[];
    const int b = blockIdx.y;
    const float* xb = x + (size_t)b * NN * 3;
    const int tid = threadIdx.x, lane = tid & 31, w = tid >> 5;

    for (int t = tid; t < NN; t += 512) {
        float px = xb[t * 3 + 0], py = xb[t * 3 + 1], pz = xb[t * 3 + 2];
        pts[t] = make_float4(px, py, pz, px * px + py * py + pz * pz);
    }
    __syncthreads();

    const int i = blockIdx.x * QPB + w;
    float4 q = pts[i];
    const float qx = 2.f * q.x, qy = 2.f * q.y, qz = 2.f * q.z;

    unsigned my_k = (lane < KK) ? okey(-FLT_MAX) : okey(FLT_MAX);
    int      my_j = 0x7fff0000 | lane;
    unsigned wkey = okey(-FLT_MAX);

    for (int jc = 0; jc < NN; jc += 32) {
        float4 p = pts[jc + lane];
        float s = fmaf(qx, p.x, fmaf(qy, p.y, fmaf(qz, p.z, -p.w)));
        unsigned k = okey(s);
        unsigned mask = __ballot_sync(0xffffffffu, k > wkey);
        while (mask) {
            const int l = __ffs(mask) - 1;
            mask &= mask - 1;
            const unsigned kc = __shfl_sync(0xffffffffu, k, l);
            if (kc > wkey) {
                const unsigned umin = __reduce_min_sync(0xffffffffu, my_k);
                const bool tied = (my_k == umin);
                const int jmax = __reduce_max_sync(0xffffffffu, tied ? my_j : -1);
                if (tied && my_j == jmax) { my_k = kc; my_j = jc + l; }
                wkey = __reduce_min_sync(0xffffffffu, my_k);
            }
        }
    }

    if (lane < KK)
        idxo[((size_t)b * NN + i) * KK + lane] = my_j;
}

// ---------------------------------------------------------------------------
// stats1: accumulate f-moments over all P positions (R13-proven numerics).
// f = (xj-xi, xi). Outputs 27 block-partials: S[0..5], M upper-tri.
// ---------------------------------------------------------------------------
__global__ void __launch_bounds__(256) stats1_kernel(
    const float* __restrict__ x, const int* __restrict__ idx,
    float* __restrict__ pf)
{
    const int tid  = threadIdx.x;
    const int lane = tid & 31;
    const int warp = tid >> 5;
    const int p  = blockIdx.x * 256 + tid;
    const int bn = p / KK;
    const int b  = bn >> 12;
    const int j  = idx[p];

    const float* xi = x + (size_t)bn * 3;
    const float* xj = x + ((size_t)b * NN + j) * 3;
    float f[6];
    f[3] = xi[0]; f[4] = xi[1]; f[5] = xi[2];
    f[0] = xj[0] - f[3]; f[1] = xj[1] - f[4]; f[2] = xj[2] - f[5];

    float acc[27];
#pragma unroll
    for (int d = 0; d < 6; d++) acc[d] = f[d];
    {
        int k = 6;
#pragma unroll
        for (int d = 0; d < 6; d++)
#pragma unroll
            for (int e = d; e < 6; e++) acc[k++] = f[d] * f[e];
    }

    __shared__ float s_m[27 * 8];
#pragma unroll
    for (int s = 0; s < 27; s++) {
        float v = acc[s];
#pragma unroll
        for (int m = 16; m > 0; m >>= 1)
            v += __shfl_xor_sync(0xffffffffu, v, m);
        if (lane == 0) s_m[s * 8 + warp] = v;
    }
    __syncthreads();

    if (tid < 27) {
        float a = 0.f;
#pragma unroll
        for (int w = 0; w < 8; w++) a += s_m[tid * 8 + w];
        pf[tid * NB1 + blockIdx.x] = a;
    }
}

// ---------------------------------------------------------------------------
// affine1 v2: warp-parallel moment reduction (no serialized barriers),
// then analytic BN1 affine. 256 threads: warp w owns stats {w, w+8, w+16, w+24}.
// ---------------------------------------------------------------------------
__global__ void affine1_kernel(const float* __restrict__ pf,
                               const float* __restrict__ W1,
                               const float* __restrict__ b1,
                               const float* __restrict__ g1,
                               const float* __restrict__ be1,
                               float* __restrict__ sc,
                               float* __restrict__ sh)
{
    __shared__ double st[32];
    const int lane = threadIdx.x & 31;
    const int warp = threadIdx.x >> 5;

#pragma unroll
    for (int g = 0; g < 4; ++g) {
        const int s = warp + g * 8;
        if (s < 27) {
            double a = 0.0;
            for (int i = lane; i < NB1; i += 32)
                a += (double)pf[s * NB1 + i];
#pragma unroll
            for (int m = 16; m > 0; m >>= 1)
                a += __shfl_xor_sync(0xffffffffu, a, m);
            if (lane == 0) st[s] = a;
        }
    }
    __syncthreads();

    if (threadIdx.x < 64) {
        const int c = threadIdx.x;
        double w[6];
#pragma unroll
        for (int d = 0; d < 6; d++) w[d] = (double)W1[c * 6 + d];
        const double b = (double)b1[c];
        double ws = 0.0;
#pragma unroll
        for (int d = 0; d < 6; d++) ws += w[d] * st[d];
        double wmw = 0.0;
        int k = 6;
#pragma unroll
        for (int d = 0; d < 6; d++)
#pragma unroll
            for (int e = d; e < 6; e++, k++)
                wmw += ((d == e) ? w[d] * w[d] : 2.0 * w[d] * w[e]) * st[k];
        const double Pd = (double)PP;
        double mean = ws / Pd + b;
        double e2   = (wmw + 2.0 * b * ws) / Pd + b * b;
        double var  = e2 - mean * mean;
        double inv  = (double)g1[c] / sqrt(var + 1e-5);
        sc[c] = (float)inv;
        sh[c] = (float)((double)be1[c] - mean * inv);
    }
}

// ---------------------------------------------------------------------------
// Reduce per-block partials -> fused BN affine (BN2/BN3; proven).
// ---------------------------------------------------------------------------
__global__ void reduce_kernel(const float* __restrict__ ps,
                              const float* __restrict__ pq, int nb,
                              const float* __restrict__ gamma,
                              const float* __restrict__ beta,
                              float* __restrict__ scale,
                              float* __restrict__ shift)
{
    const int c = blockIdx.x;
    double s = 0.0, q = 0.0;
    for (int i = threadIdx.x; i < nb; i += 256) {
        s += (double)ps[c * nb + i];
        q += (double)pq[c * nb + i];
    }
    __shared__ double r1[256], r2[256];
    r1[threadIdx.x] = s; r2[threadIdx.x] = q;
    __syncthreads();
    for (int off = 128; off > 0; off >>= 1) {
        if (threadIdx.x < off) {
            r1[threadIdx.x] += r1[threadIdx.x + off];
            r2[threadIdx.x] += r2[threadIdx.x + off];
        }
        __syncthreads();
    }
    if (threadIdx.x == 0) {
        double mean = r1[0] / (double)PP;
        double var  = r2[0] / (double)PP - mean * mean;
        double inv  = (double)gamma[c] / sqrt(var + 1e-5);
        scale[c] = (float)inv;
        shift[c] = (float)((double)beta[c] - mean * inv);
    }
}

// ---------------------------------------------------------------------------
// Fused conv1+BN1+relu+conv2 GEMM (R13-measured 153.6us — unchanged).
// ---------------------------------------------------------------------------
__global__ void __launch_bounds__(256, 2) gemm_fused_kernel(
    const float* __restrict__ x,
    const int* __restrict__ idx,
    const float* __restrict__ W1,
    const float* __restrict__ b1,
    const float* __restrict__ sc1,
    const float* __restrict__ sh1,
    const float* __restrict__ W,     // W2 [128][64]
    const float* __restrict__ bias,  // b2
    float* __restrict__ yout,
    float* __restrict__ ps,
    float* __restrict__ pq)
{
    extern __shared__ float sh[];
    float* Wsh   = sh;                     // [64][132] transposed W2
    float* Ash   = Wsh + 64 * 132;         // [64][128]
    float* fs    = Ash + 64 * 128;         // [128][7]
    float* W1sh  = fs + 128 * 7;           // [64][6]
    float* b1sh  = W1sh + 64 * 6;          // [64]
    float* sc1sh = b1sh + 64;              // [64]
    float* sh1sh = sc1sh + 64;             // [64]
    const int tid = threadIdx.x;

    for (int t = tid; t < 128 * 64; t += 256) {
        int o = t >> 6, c = t & 63;
        Wsh[c * 132 + o] = W[t];
    }
    for (int t = tid; t < 64 * 6; t += 256) W1sh[t] = W1[t];
    if (tid < 64) {
        b1sh[tid]  = b1[tid];
        sc1sh[tid] = sc1[tid];
        sh1sh[tid] = sh1[tid];
    }

    const int pbase = blockIdx.x * 128;
    if (tid < 128) {
        const int p  = pbase + tid;
        const int bn = p / KK;
        const int b  = bn >> 12;
        const int j  = idx[p];
        const float* xi = x + (size_t)bn * 3;
        const float* xj = x + ((size_t)b * NN + j) * 3;
        float xi0 = xi[0], xi1 = xi[1], xi2 = xi[2];
        fs[tid * 7 + 0] = xj[0] - xi0;
        fs[tid * 7 + 1] = xj[1] - xi1;
        fs[tid * 7 + 2] = xj[2] - xi2;
        fs[tid * 7 + 3] = xi0;
        fs[tid * 7 + 4] = xi1;
        fs[tid * 7 + 5] = xi2;
    }
    __syncthreads();

    for (int t = tid; t < 64 * 128; t += 256) {
        int c = t >> 7, p = t & 127;
        const float* w = W1sh + c * 6;
        const float* f = fs + p * 7;
        float a = b1sh[c];
        a = fmaf(w[0], f[0], a);
        a = fmaf(w[1], f[1], a);
        a = fmaf(w[2], f[2], a);
        a = fmaf(w[3], f[3], a);
        a = fmaf(w[4], f[4], a);
        a = fmaf(w[5], f[5], a);
        Ash[t] = fmaxf(fmaf(a, sc1sh[c], sh1sh[c]), 0.f);
    }
    __syncthreads();

    const int tx = tid & 15;
    const int ty = tid >> 4;

    unsigned long long acc[8][4];
#pragma unroll
    for (int i = 0; i < 8; i++)
#pragma unroll
        for (int jp = 0; jp < 4; jp++) acc[i][jp] = 0ULL;

#pragma unroll 4
    for (int c = 0; c < 64; ++c) {
        ulonglong2 A0 = *(const ulonglong2*)(Ash + c * 128 + tx * 4);
        ulonglong2 A1 = *(const ulonglong2*)(Ash + c * 128 + 64 + tx * 4);
        unsigned long long av[4] = {A0.x, A0.y, A1.x, A1.y};
        float4 w0 = *(const float4*)(Wsh + c * 132 + ty * 4);
        float4 w1 = *(const float4*)(Wsh + c * 132 + 64 + ty * 4);
        float wf[8] = {w0.x, w0.y, w0.z, w0.w, w1.x, w1.y, w1.z, w1.w};
#pragma unroll
        for (int i = 0; i < 8; i++) {
            unsigned long long wsp = splat2(wf[i]);
#pragma unroll
            for (int jp = 0; jp < 4; jp++) ffma2(acc[i][jp], wsp, av[jp]);
        }
    }

#pragma unroll
    for (int i = 0; i < 8; i++) {
        const int o = (i < 4) ? (ty * 4 + i) : (64 + ty * 4 + (i - 4));
        const float bo = bias[o];
        float2 p0 = unpack2(acc[i][0]);
        float2 p1 = unpack2(acc[i][1]);
        float2 p2 = unpack2(acc[i][2]);
        float2 p3 = unpack2(acc[i][3]);
        float v0 = p0.x + bo, v1 = p0.y + bo, v2 = p1.x + bo, v3 = p1.y + bo;
        float v4 = p2.x + bo, v5 = p2.y + bo, v6 = p3.x + bo, v7 = p3.y + bo;
        float* dst = yout + (size_t)o * PP + pbase;
        *(float4*)(dst + tx * 4)      = make_float4(v0, v1, v2, v3);
        *(float4*)(dst + 64 + tx * 4) = make_float4(v4, v5, v6, v7);

        float s = v0 + v1 + v2 + v3 + v4 + v5 + v6 + v7;
        float q = v0 * v0 + v1 * v1 + v2 * v2 + v3 * v3
                + v4 * v4 + v5 * v5 + v6 * v6 + v7 * v7;
#pragma unroll
        for (int m = 8; m > 0; m >>= 1) {
            s += __shfl_xor_sync(0xffffffffu, s, m, 16);
            q += __shfl_xor_sync(0xffffffffu, q, m, 16);
        }
        if (tx == 0) {
            ps[(size_t)o * NBG + blockIdx.x] = s;
            pq[(size_t)o * NBG + blockIdx.x] = q;
        }
    }
}

// ---------------------------------------------------------------------------
// GEMM (proven): FFMA2 inner loop, 64-deep k-chunks, 2 blocks/SM. CIN=128.
// ---------------------------------------------------------------------------
template <int CIN>
__global__ void __launch_bounds__(256, 2) gemm_kernel(
    const float* __restrict__ yin,
    const float* __restrict__ W,
    const float* __restrict__ bias,
    const float* __restrict__ scale,
    const float* __restrict__ shift,
    float* __restrict__ yout,
    float* __restrict__ ps,
    float* __restrict__ pq)
{
    extern __shared__ float sh[];
    float* Wsh = sh;                  // transposed [CIN][132]
    float* Ash = sh + 132 * CIN;      // [64][128] k-chunk
    const int tid = threadIdx.x;

    for (int t = tid; t < 128 * CIN; t += 256) {
        int o = t / CIN, c = t - o * CIN;
        Wsh[c * 132 + o] = W[t];
    }

    const int pbase = blockIdx.x * 128;
    const int tx = tid & 15;
    const int ty = tid >> 4;

    unsigned long long acc[8][4];
#pragma unroll
    for (int i = 0; i < 8; i++)
#pragma unroll
        for (int jp = 0; jp < 4; jp++) acc[i][jp] = 0ULL;

#pragma unroll
    for (int kc = 0; kc < CIN / 64; ++kc) {
        __syncthreads();
        for (int t = tid; t < 64 * 128; t += 256) {
            int c = t >> 7, p = t & 127;
            int cg = kc * 64 + c;
            float v = yin[(size_t)cg * PP + pbase + p];
            v = fmaf(v, scale[cg], shift[cg]);
            Ash[t] = fmaxf(v, 0.f);
        }
        __syncthreads();

#pragma unroll 4
        for (int c = 0; c < 64; ++c) {
            const int cg = kc * 64 + c;
            ulonglong2 A0 = *(const ulonglong2*)(Ash + c * 128 + tx * 4);
            ulonglong2 A1 = *(const ulonglong2*)(Ash + c * 128 + 64 + tx * 4);
            unsigned long long av[4] = {A0.x, A0.y, A1.x, A1.y};
            float4 w0 = *(const float4*)(Wsh + cg * 132 + ty * 4);
            float4 w1 = *(const float4*)(Wsh + cg * 132 + 64 + ty * 4);
            float wf[8] = {w0.x, w0.y, w0.z, w0.w, w1.x, w1.y, w1.z, w1.w};
#pragma unroll
            for (int i = 0; i < 8; i++) {
                unsigned long long wsp = splat2(wf[i]);
#pragma unroll
                for (int jp = 0; jp < 4; jp++) ffma2(acc[i][jp], wsp, av[jp]);
            }
        }
    }

#pragma unroll
    for (int i = 0; i < 8; i++) {
        const int o = (i < 4) ? (ty * 4 + i) : (64 + ty * 4 + (i - 4));
        const float bo = bias[o];
        float2 p0 = unpack2(acc[i][0]);
        float2 p1 = unpack2(acc[i][1]);
        float2 p2 = unpack2(acc[i][2]);
        float2 p3 = unpack2(acc[i][3]);
        float v0 = p0.x + bo, v1 = p0.y + bo, v2 = p1.x + bo, v3 = p1.y + bo;
        float v4 = p2.x + bo, v5 = p2.y + bo, v6 = p3.x + bo, v7 = p3.y + bo;
        float* dst = yout + (size_t)o * PP + pbase;
        *(float4*)(dst + tx * 4)      = make_float4(v0, v1, v2, v3);
        *(float4*)(dst + 64 + tx * 4) = make_float4(v4, v5, v6, v7);

        float s = v0 + v1 + v2 + v3 + v4 + v5 + v6 + v7;
        float q = v0 * v0 + v1 * v1 + v2 * v2 + v3 * v3
                + v4 * v4 + v5 * v5 + v6 * v6 + v7 * v7;
#pragma unroll
        for (int m = 8; m > 0; m >>= 1) {
            s += __shfl_xor_sync(0xffffffffu, s, m, 16);
            q += __shfl_xor_sync(0xffffffffu, q, m, 16);
        }
        if (tx == 0) {
            ps[(size_t)o * NBG + blockIdx.x] = s;
            pq[(size_t)o * NBG + blockIdx.x] = q;
        }
    }
}

// ---------------------------------------------------------------------------
// Max over k with final BN affine applied elementwise (proven).
// ---------------------------------------------------------------------------
__global__ void maxk_kernel(const float* __restrict__ y3,
                            const float* __restrict__ scale,
                            const float* __restrict__ shift,
                            float* __restrict__ out)
{
    const int n = blockIdx.x * blockDim.x + threadIdx.x;
    const int o = blockIdx.y;
    const int b = blockIdx.z;
    const float sc = scale[o], sf = shift[o];
    const float4* base =
        (const float4*)(y3 + (size_t)o * PP + ((size_t)b * NN + n) * KK);
    float m = -FLT_MAX;
#pragma unroll
    for (int q = 0; q < 5; ++q) {
        float4 v = base[q];
        m = fmaxf(m, fmaf(v.x, sc, sf));
        m = fmaxf(m, fmaf(v.y, sc, sf));
        m = fmaxf(m, fmaf(v.z, sc, sf));
        m = fmaxf(m, fmaf(v.w, sc, sf));
    }
    out[((size_t)b * 128 + o) * NN + n] = m;
}

// ---------------------------------------------------------------------------
// Launcher: graph-capturable, allocation-free.
// ---------------------------------------------------------------------------
extern "C" void kernel_launch(void* const* d_in, const int* in_sizes, int n_in,
                              void* d_out, int out_size)
{
    const float* x   = (const float*)d_in[0];
    const float* W1  = (const float*)d_in[1];
    const float* b1  = (const float*)d_in[2];
    const float* g1  = (const float*)d_in[3];
    const float* be1 = (const float*)d_in[4];
    const float* W2  = (const float*)d_in[5];
    const float* b2  = (const float*)d_in[6];
    const float* g2  = (const float*)d_in[7];
    const float* be2 = (const float*)d_in[8];
    const float* W3  = (const float*)d_in[9];
    const float* b3  = (const float*)d_in[10];
    const float* g3  = (const float*)d_in[11];
    const float* be3 = (const float*)d_in[12];
    float* out = (float*)d_out;

    void *y2p, *y3p, *idxp, *psp, *pqp;
    void *sc1p, *sh1p, *sc2p, *sh2p, *sc3p, *sh3p;
    cudaGetSymbolAddress(&y2p,  g_y2);
    cudaGetSymbolAddress(&y3p,  g_y3);
    cudaGetSymbolAddress(&idxp, g_idx);
    cudaGetSymbolAddress(&psp,  g_ps);
    cudaGetSymbolAddress(&pqp,  g_pq);
    cudaGetSymbolAddress(&sc1p, g_sc1);  cudaGetSymbolAddress(&sh1p, g_sh1);
    cudaGetSymbolAddress(&sc2p, g_sc2);  cudaGetSymbolAddress(&sh2p, g_sh2);
    cudaGetSymbolAddress(&sc3p, g_sc3);  cudaGetSymbolAddress(&sh3p, g_sh3);

    const int smemF   = (64 * 132 + 64 * 128 + 128 * 7 + 64 * 6 + 3 * 64) * 4; // 72448
    const int smem128 = (132 * 128 + 64 * 128) * 4;                             // 100352
    cudaFuncSetAttribute(knn_warp_kernel,  cudaFuncAttributeMaxDynamicSharedMemorySize, 65536);
    cudaFuncSetAttribute(gemm_fused_kernel,cudaFuncAttributeMaxDynamicSharedMemorySize, smemF);
    cudaFuncSetAttribute(gemm_kernel<128>, cudaFuncAttributeMaxDynamicSharedMemorySize, smem128);

    // K0: warp-cooperative kNN (R9-proven)
    knn_warp_kernel<<<dim3(NN / QPB, BB), 512, 65536>>>(x, (int*)idxp);

    // BN1 via f-moments (analytic; y1 never materialized)
    stats1_kernel<<<NB1, 256>>>(x, (const int*)idxp, (float*)psp);
    affine1_kernel<<<1, 256>>>((const float*)psp, W1, b1, g1, be1,
                               (float*)sc1p, (float*)sh1p);

    // conv1+BN1+relu+conv2 fused + BN2 partials   (launch #4 -> ncu window)
    gemm_fused_kernel<<<NBG, 256, smemF>>>(x, (const int*)idxp, W1, b1,
                                           (const float*)sc1p, (const float*)sh1p,
                                           W2, b2, (float*)y2p,
                                           (float*)psp, (float*)pqp);
    reduce_kernel<<<128, 256>>>((const float*)psp, (const float*)pqp, NBG,
                                g2, be2, (float*)sc2p, (float*)sh2p);

    // conv3 on relu(BN2(y2)) + BN3 partials
    gemm_kernel<128><<<NBG, 256, smem128>>>((const float*)y2p, W3, b3,
                                            (const float*)sc2p, (const float*)sh2p,
                                            (float*)y3p, (float*)psp, (float*)pqp);
    reduce_kernel<<<128, 256>>>((const float*)psp, (const float*)pqp, NBG,
                                g3, be3, (float*)sc3p, (float*)sh3p);

    // BN3 affine + max over k
    maxk_kernel<<<dim3(NN / 256, 128, BB), 256>>>((const float*)y3p,
                                                  (const float*)sc3p, (const float*)sh3p,
                                                  out);
}